// round 1
// baseline (speedup 1.0000x reference)
#include <cuda_runtime.h>
#include <math.h>

#define N_EDGES_C 262144
#define N_NODES_C 50000
#define EMB 512
#define DIN 1536
#define FFDIM 1024
#define NGRAPH 64

#define BM 128
#define BN 128
#define BK 8
#define NKT (DIN / BK)   // 192 k-tiles per FF tile
#define NTILES 16        // 2048 total FF cols / BN

__device__ __forceinline__ float gelu_tanh(float x) {
    // jax.nn.gelu default (approximate=True): 0.5*x*(1+tanh(sqrt(2/pi)*(x+0.044715 x^3)))
    float inner = fmaf(0.044715f * x * x, x, x);
    float u = 0.7978845608028654f * inner;
    float t;
    asm("tanh.approx.f32 %0, %1;" : "=f"(t) : "f"(u));
    return 0.5f * x * (1.0f + t);
}

__global__ void zero_out_kernel(float* __restrict__ out, int n) {
    int i = blockIdx.x * blockDim.x + threadIdx.x;
    if (i < n) out[i] = 0.0f;
}

// One block = 128 edges. Loops over all 16 FF tiles (8 for energy MLP, 8 for
// force MLP), runs a 128x128x8 double-buffered FP32 GEMM per tile, fuses
// bias+gelu+W2-dot into per-edge scalar accumulators, then scatters.
__global__ __launch_bounds__(256, 2) void fused_edge_mlp(
    const float* __restrict__ x, const float* __restrict__ pos,
    const float* __restrict__ W1e, const float* __restrict__ b1e,
    const float* __restrict__ W2e, const float* __restrict__ b2e,
    const float* __restrict__ W1f, const float* __restrict__ b1f,
    const float* __restrict__ W2f, const float* __restrict__ b2f,
    const int* __restrict__ batch, const int* __restrict__ edge_index,
    float* __restrict__ out)
{
    __shared__ float As[2][BK][132];   // padded stride 132: conflict-free transposed stores
    __shared__ float Bs[2][BK][BN];
    __shared__ int s_src[BM];
    __shared__ int s_dst[BM];

    const int tid = threadIdx.x;
    const int tx = tid & 15;          // FF-col group
    const int ty = tid >> 4;          // edge-row group
    const int e0 = blockIdx.x * BM;

    if (tid < BM) {
        s_src[tid] = edge_index[e0 + tid];
        s_dst[tid] = edge_index[N_EDGES_C + e0 + tid];
    }
    __syncthreads();

    // A-tile loader assignment: each thread owns one float4 of the 128x8 tile
    const int arow = tid >> 1;             // 0..127
    const int akq  = (tid & 1) * 4;        // 0 or 4
    const float* baseS = x + (size_t)s_src[arow] * EMB;
    const float* baseD = x + (size_t)s_dst[arow] * EMB;
    const float* baseE = x + ((size_t)N_NODES_C + (size_t)(e0 + arow)) * EMB;

    // B-tile loader assignment: one float4 of the 8x128 tile
    const int bk = tid >> 5;               // 0..7
    const int bc = (tid & 31) * 4;         // 0..124

    float se[8], sf[8];
    #pragma unroll
    for (int i = 0; i < 8; i++) { se[i] = 0.0f; sf[i] = 0.0f; }

    for (int nt = 0; nt < NTILES; ++nt) {
        const bool isE = (nt < 8);
        const float* W1 = isE ? W1e : W1f;
        const float* b1 = isE ? b1e : b1f;
        const float* W2 = isE ? W2e : W2f;
        const int colbase = (nt & 7) * BN;

        float acc[8][8];
        #pragma unroll
        for (int i = 0; i < 8; i++)
            #pragma unroll
            for (int j = 0; j < 8; j++) acc[i][j] = 0.0f;

        // ---- preload kt = 0 (gk < 512 always => src segment) ----
        float4 pa = *(const float4*)(baseS + akq);
        float4 pb = *(const float4*)&W1[(size_t)bk * FFDIM + colbase + bc];
        As[0][akq + 0][arow] = pa.x;
        As[0][akq + 1][arow] = pa.y;
        As[0][akq + 2][arow] = pa.z;
        As[0][akq + 3][arow] = pa.w;
        *(float4*)&Bs[0][bk][bc] = pb;
        __syncthreads();

        int buf = 0;
        for (int kt = 0; kt < NKT; ++kt) {
            // prefetch next k-tile while computing on current one
            if (kt + 1 < NKT) {
                const int gk = (kt + 1) * BK + akq;   // whole 8-chunk stays in one segment
                const float* p = (gk < 512)  ? (baseS + gk)
                               : (gk < 1024) ? (baseD + (gk - 512))
                                             : (baseE + (gk - 1024));
                pa = *(const float4*)p;
                pb = *(const float4*)&W1[((size_t)(kt + 1) * BK + bk) * FFDIM + colbase + bc];
            }

            #pragma unroll
            for (int kk = 0; kk < BK; kk++) {
                float4 a0 = *(const float4*)&As[buf][kk][ty * 8];
                float4 a1 = *(const float4*)&As[buf][kk][ty * 8 + 4];
                float4 c0 = *(const float4*)&Bs[buf][kk][tx * 8];
                float4 c1 = *(const float4*)&Bs[buf][kk][tx * 8 + 4];
                float av[8] = {a0.x, a0.y, a0.z, a0.w, a1.x, a1.y, a1.z, a1.w};
                float bv[8] = {c0.x, c0.y, c0.z, c0.w, c1.x, c1.y, c1.z, c1.w};
                #pragma unroll
                for (int i = 0; i < 8; i++)
                    #pragma unroll
                    for (int j = 0; j < 8; j++)
                        acc[i][j] = fmaf(av[i], bv[j], acc[i][j]);
            }

            if (kt + 1 < NKT) {
                const int nb = buf ^ 1;
                As[nb][akq + 0][arow] = pa.x;
                As[nb][akq + 1][arow] = pa.y;
                As[nb][akq + 2][arow] = pa.z;
                As[nb][akq + 3][arow] = pa.w;
                *(float4*)&Bs[nb][bk][bc] = pb;
            }
            __syncthreads();
            buf ^= 1;
        }

        // ---- fused second layer: bias + gelu + dot with W2 column ----
        const int colg = colbase + tx * 8;
        float b1v[8], w2v[8];
        #pragma unroll
        for (int j = 0; j < 8; j++) {
            b1v[j] = b1[colg + j];
            w2v[j] = W2[colg + j];
        }
        if (isE) {
            #pragma unroll
            for (int i = 0; i < 8; i++)
                #pragma unroll
                for (int j = 0; j < 8; j++)
                    se[i] = fmaf(gelu_tanh(acc[i][j] + b1v[j]), w2v[j], se[i]);
        } else {
            #pragma unroll
            for (int i = 0; i < 8; i++)
                #pragma unroll
                for (int j = 0; j < 8; j++)
                    sf[i] = fmaf(gelu_tanh(acc[i][j] + b1v[j]), w2v[j], sf[i]);
        }
    }

    // ---- reduce across the 16 tx threads sharing the same edge rows ----
    #pragma unroll
    for (int m = 1; m < 16; m <<= 1) {
        #pragma unroll
        for (int i = 0; i < 8; i++) {
            se[i] += __shfl_xor_sync(0xffffffffu, se[i], m);
            sf[i] += __shfl_xor_sync(0xffffffffu, sf[i], m);
        }
    }

    if (tx == 0) {
        const float b2ev = b2e[0];
        const float b2fv = b2f[0];
        float* outE = out;            // [64]
        float* outF = out + NGRAPH;   // [50000, 3]
        #pragma unroll
        for (int i = 0; i < 8; i++) {
            const int r = ty * 8 + i;
            const int s = s_src[r];
            const int d = s_dst[r];
            const float Ev = se[i] + b2ev;
            const float Fv = sf[i] + b2fv;
            const float vx = pos[3 * s + 0] - pos[3 * d + 0];
            const float vy = pos[3 * s + 1] - pos[3 * d + 1];
            const float vz = pos[3 * s + 2] - pos[3 * d + 2];
            const float n = sqrtf(vx * vx + vy * vy + vz * vz);
            const float inv = 1.0f / fmaxf(n, 1e-12f);
            atomicAdd(&outE[batch[s]], Ev);
            atomicAdd(&outF[3 * s + 0], Fv * vx * inv);
            atomicAdd(&outF[3 * s + 1], Fv * vy * inv);
            atomicAdd(&outF[3 * s + 2], Fv * vz * inv);
        }
    }
}

extern "C" void kernel_launch(void* const* d_in, const int* in_sizes, int n_in,
                              void* d_out, int out_size) {
    const float* x    = (const float*)d_in[0];
    const float* pos  = (const float*)d_in[1];
    const float* W1e  = (const float*)d_in[2];
    const float* b1e  = (const float*)d_in[3];
    const float* W2e  = (const float*)d_in[4];
    const float* b2e  = (const float*)d_in[5];
    const float* W1f  = (const float*)d_in[6];
    const float* b1f  = (const float*)d_in[7];
    const float* W2f  = (const float*)d_in[8];
    const float* b2f  = (const float*)d_in[9];
    const int* batch  = (const int*)d_in[10];
    const int* eidx   = (const int*)d_in[11];
    float* out = (float*)d_out;

    // Output layout: energy [64] followed by forces [50000*3]. Zero it
    // (d_out is poisoned; scatter-adds need a zeroed base).
    zero_out_kernel<<<(out_size + 255) / 256, 256>>>(out, out_size);

    fused_edge_mlp<<<N_EDGES_C / BM, 256>>>(
        x, pos, W1e, b1e, W2e, b2e, W1f, b1f, W2f, b2f, batch, eidx, out);
}

// round 3
// speedup vs baseline: 3.0406x; 3.0406x over previous
#include <cuda_runtime.h>
#include <cstdint>
#include <math.h>

#define EDGES   262144
#define NODES   50000
#define EMB     512
#define KDIM    1536
#define FF      1024
#define NGR     64

#define BM      128            // edges per CTA
#define BN      256            // ff cols per pass
#define BK      16             // K floats per stage
#define NPASS   8              // 2048 total ff cols / BN
#define KT      96             // K stages per pass (1536/16)
#define G_TOTAL (NPASS * KT)   // 768
#define A_BYTES (BM * BK * 4)  // 8 KB
#define B_BYTES (BN * BK * 4)  // 16 KB
#define STAGE_BYTES (A_BYTES + B_BYTES)
#define NSTAGE  4

__device__ float g_W1T[2048 * 1536];   // W1e|W1f transposed to [n][k], tf32-rounded

__device__ __forceinline__ uint32_t smem_u32(const void* p) {
    uint32_t a;
    asm("{ .reg .u64 t; cvta.to.shared.u64 t, %1; cvt.u32.u64 %0, t; }" : "=r"(a) : "l"(p));
    return a;
}
__device__ __forceinline__ uint32_t f2tf32(float f) {
    uint32_t r; asm("cvt.rna.tf32.f32 %0, %1;" : "=r"(r) : "f"(f)); return r;
}
__device__ __forceinline__ float gelu_tanh(float x) {
    float inner = fmaf(0.044715f * x * x, x, x);
    float u = 0.7978845608028654f * inner;
    float t; asm("tanh.approx.f32 %0, %1;" : "=f"(t) : "f"(u));
    return 0.5f * x * (1.0f + t);
}
__device__ __forceinline__ void cp16(uint32_t dst, const void* src) {
    asm volatile("cp.async.cg.shared.global [%0], [%1], 16;" :: "r"(dst), "l"(src));
}
#define CP_COMMIT() asm volatile("cp.async.commit_group;" ::: "memory")
#define CP_WAIT2()  asm volatile("cp.async.wait_group 2;" ::: "memory")

__device__ __forceinline__ void mma8(float* d, uint32_t a0, uint32_t a1, uint32_t a2,
                                     uint32_t a3, uint32_t b0, uint32_t b1) {
    asm volatile(
        "mma.sync.aligned.m16n8k8.row.col.f32.tf32.tf32.f32 "
        "{%0,%1,%2,%3},{%4,%5,%6,%7},{%8,%9},{%0,%1,%2,%3};"
        : "+f"(d[0]), "+f"(d[1]), "+f"(d[2]), "+f"(d[3])
        : "r"(a0), "r"(a1), "r"(a2), "r"(a3), "r"(b0), "r"(b1));
}

__global__ void zero_out_kernel(float* __restrict__ out, int n) {
    int i = blockIdx.x * blockDim.x + threadIdx.x;
    if (i < n) out[i] = 0.0f;
}

// Transpose W1e/W1f [1536,1024] -> g_W1T [2048,1536] (n-major, k-contiguous), tf32 rna.
__global__ void transpose_w1(const float* __restrict__ W1e, const float* __restrict__ W1f) {
    __shared__ float t[32][33];
    const float* W = blockIdx.z ? W1f : W1e;
    const int k0 = blockIdx.x * 32, n0 = blockIdx.y * 32;
    const int tx = threadIdx.x, ty0 = threadIdx.y;
    #pragma unroll
    for (int r = 0; r < 4; r++) {
        int ty = ty0 + r * 8;
        t[ty][tx] = W[(size_t)(k0 + ty) * FF + n0 + tx];
    }
    __syncthreads();
    #pragma unroll
    for (int r = 0; r < 4; r++) {
        int ty = ty0 + r * 8;
        g_W1T[(size_t)(blockIdx.z * FF + n0 + ty) * KDIM + k0 + tx] =
            __uint_as_float(f2tf32(t[tx][ty]));
    }
}

__global__ __launch_bounds__(256, 1) void fused_edge_mlp_mma(
    const float* __restrict__ x, const float* __restrict__ pos,
    const float* __restrict__ b1e, const float* __restrict__ W2e, const float* __restrict__ b2e,
    const float* __restrict__ b1f, const float* __restrict__ W2f, const float* __restrict__ b2f,
    const int* __restrict__ batch, const int* __restrict__ edge_index,
    float* __restrict__ out)
{
    extern __shared__ char sm[];
    __shared__ int s_src[BM], s_dst[BM];
    __shared__ float s_accE[BM], s_accF[BM], s_energy[NGR];

    const int tid  = threadIdx.x;
    const int wid  = tid >> 5;
    const int lane = tid & 31;
    const int e0   = blockIdx.x * BM;

    if (tid < BM) {
        s_src[tid] = edge_index[e0 + tid];
        s_dst[tid] = edge_index[EDGES + e0 + tid];
        s_accE[tid] = 0.0f; s_accF[tid] = 0.0f;
    }
    if (tid < NGR) s_energy[tid] = 0.0f;
    __syncthreads();

    // ---- loader assignments: 16B chunk index qa, A rows {r0, r0+64}, B rows {r0+64j} ----
    const int qa = tid & 3;
    const int r0 = tid >> 2;           // 0..63
    const float* aS0 = x + (size_t)s_src[r0] * EMB;
    const float* aD0 = x + (size_t)s_dst[r0] * EMB;
    const float* aE0 = x + ((size_t)NODES + e0 + r0) * EMB;
    const float* aS1 = x + (size_t)s_src[r0 + 64] * EMB;
    const float* aD1 = x + (size_t)s_dst[r0 + 64] * EMB;
    const float* aE1 = x + ((size_t)NODES + e0 + r0 + 64) * EMB;

    const uint32_t smem_base = smem_u32(sm);

    // stage issue: A[128x16] + B[256x16], 16B cp.async chunks, k-contiguous rows
    auto issue = [&](int g) {
        const int pass = g / KT;
        const int kt   = g - pass * KT;
        const int kpos = kt * BK;
        const int seg  = kpos >> 9;                 // 0:src 1:dst 2:edge
        const int koff = (kpos & 511) + qa * 4;
        const uint32_t st = smem_base + (g & 3) * STAGE_BYTES;
        const float* p0 = (seg == 0) ? aS0 : (seg == 1) ? aD0 : aE0;
        const float* p1 = (seg == 0) ? aS1 : (seg == 1) ? aD1 : aE1;
        cp16(st + (uint32_t)r0 * 64 + qa * 16, p0 + koff);
        cp16(st + (uint32_t)(r0 + 64) * 64 + qa * 16, p1 + koff);
        const float* wb = g_W1T + (size_t)(pass * BN) * KDIM + kpos + qa * 4;
        #pragma unroll
        for (int j = 0; j < 4; j++) {
            const int row = r0 + 64 * j;
            cp16(st + A_BYTES + (uint32_t)row * 64 + qa * 16,
                 wb + (size_t)row * KDIM);
        }
        CP_COMMIT();
    };

    issue(0); issue(1); issue(2);

    // ---- warp tiling: 2(M) x 4(N) warps, 64x64 each ----
    const int warp_m = wid & 1;
    const int warp_n = wid >> 1;
    const int lq = lane >> 2;   // 0..7
    const int lc = lane & 3;    // 0..3

    float acc[4][8][4];
    #pragma unroll
    for (int i = 0; i < 4; i++)
        #pragma unroll
        for (int j = 0; j < 8; j++)
            #pragma unroll
            for (int k = 0; k < 4; k++) acc[i][j][k] = 0.0f;

    for (int g = 0; g < G_TOTAL; g++) {
        CP_WAIT2();
        __syncthreads();
        if (g + 3 < G_TOTAL) issue(g + 3);

        const char* st = sm + (g & 3) * STAGE_BYTES;
        const uint4* As = (const uint4*)st;               // [row][4] 16B chunks
        const uint4* Bs = (const uint4*)(st + A_BYTES);

        // A fragments: rows (warp_m*64 + mf*16 + lq) and +8; chunk lc covers 4 logical k
        uint4 a[4][2];
        #pragma unroll
        for (int mf = 0; mf < 4; mf++) {
            const int r = warp_m * 64 + mf * 16 + lq;
            a[mf][0] = As[r * 4 + lc];
            a[mf][1] = As[(r + 8) * 4 + lc];
        }
        #pragma unroll
        for (int nf = 0; nf < 8; nf++) {
            const int c = warp_n * 64 + nf * 8 + lq;
            const uint4 w = Bs[c * 4 + lc];
            #pragma unroll
            for (int mf = 0; mf < 4; mf++) {
                mma8(acc[mf][nf], a[mf][0].x, a[mf][1].x, a[mf][0].y, a[mf][1].y, w.x, w.y);
                mma8(acc[mf][nf], a[mf][0].z, a[mf][1].z, a[mf][0].w, a[mf][1].w, w.z, w.w);
            }
        }

        // ---- end-of-pass fused epilogue: bias + gelu + dot(W2), reduce, accumulate ----
        if ((g % KT) == KT - 1) {
            const int pass = g / KT;
            const bool isE = (pass < 4);
            const float* b1 = isE ? b1e : b1f;
            const float* w2 = isE ? W2e : W2f;
            float* sacc = isE ? s_accE : s_accF;
            const int colbase = (pass & 3) * BN + warp_n * 64;
            #pragma unroll
            for (int mf = 0; mf < 4; mf++) {
                float sLo = 0.0f, sHi = 0.0f;
                #pragma unroll
                for (int nf = 0; nf < 8; nf++) {
                    const int c0 = colbase + nf * 8 + 2 * lc;
                    const float2 bb = *(const float2*)&b1[c0];
                    const float2 ww = *(const float2*)&w2[c0];
                    sLo = fmaf(gelu_tanh(acc[mf][nf][0] + bb.x), ww.x, sLo);
                    sLo = fmaf(gelu_tanh(acc[mf][nf][1] + bb.y), ww.y, sLo);
                    sHi = fmaf(gelu_tanh(acc[mf][nf][2] + bb.x), ww.x, sHi);
                    sHi = fmaf(gelu_tanh(acc[mf][nf][3] + bb.y), ww.y, sHi);
                    acc[mf][nf][0] = 0.0f; acc[mf][nf][1] = 0.0f;
                    acc[mf][nf][2] = 0.0f; acc[mf][nf][3] = 0.0f;
                }
                sLo += __shfl_xor_sync(0xffffffffu, sLo, 1);
                sLo += __shfl_xor_sync(0xffffffffu, sLo, 2);
                sHi += __shfl_xor_sync(0xffffffffu, sHi, 1);
                sHi += __shfl_xor_sync(0xffffffffu, sHi, 2);
                if (lc == 0) {
                    const int r = warp_m * 64 + mf * 16 + lq;
                    atomicAdd(&sacc[r], sLo);
                    atomicAdd(&sacc[r + 8], sHi);
                }
            }
        }
    }

    __syncthreads();

    // ---- per-edge readout + scatter ----
    if (tid < BM) {
        const int sN = s_src[tid], dN = s_dst[tid];
        const float Ev = s_accE[tid] + b2e[0];
        const float Fv = s_accF[tid] + b2f[0];
        const float vx = pos[3 * sN + 0] - pos[3 * dN + 0];
        const float vy = pos[3 * sN + 1] - pos[3 * dN + 1];
        const float vz = pos[3 * sN + 2] - pos[3 * dN + 2];
        const float n  = sqrtf(vx * vx + vy * vy + vz * vz);
        const float inv = 1.0f / fmaxf(n, 1e-12f);
        atomicAdd(&s_energy[batch[sN]], Ev);
        float* outF = out + NGR;
        atomicAdd(&outF[3 * sN + 0], Fv * vx * inv);
        atomicAdd(&outF[3 * sN + 1], Fv * vy * inv);
        atomicAdd(&outF[3 * sN + 2], Fv * vz * inv);
    }
    __syncthreads();
    if (tid < NGR) atomicAdd(&out[tid], s_energy[tid]);
}

extern "C" void kernel_launch(void* const* d_in, const int* in_sizes, int n_in,
                              void* d_out, int out_size) {
    const float* x    = (const float*)d_in[0];
    const float* pos  = (const float*)d_in[1];
    const float* W1e  = (const float*)d_in[2];
    const float* b1e  = (const float*)d_in[3];
    const float* W2e  = (const float*)d_in[4];
    const float* b2e  = (const float*)d_in[5];
    const float* W1f  = (const float*)d_in[6];
    const float* b1f  = (const float*)d_in[7];
    const float* W2f  = (const float*)d_in[8];
    const float* b2f  = (const float*)d_in[9];
    const int* batch  = (const int*)d_in[10];
    const int* eidx   = (const int*)d_in[11];
    float* out = (float*)d_out;

    zero_out_kernel<<<(out_size + 255) / 256, 256>>>(out, out_size);

    dim3 tg(KDIM / 32, FF / 32, 2);
    transpose_w1<<<tg, dim3(32, 8)>>>(W1e, W1f);

    const int smem = NSTAGE * STAGE_BYTES;   // 96 KB dynamic
    cudaFuncSetAttribute(fused_edge_mlp_mma, cudaFuncAttributeMaxDynamicSharedMemorySize, smem);

    fused_edge_mlp_mma<<<EDGES / BM, 256, smem>>>(
        x, pos, b1e, W2e, b2e, b1f, W2f, b2f, batch, eidx, out);
}

// round 4
// speedup vs baseline: 5.7274x; 1.8837x over previous
#include <cuda_runtime.h>
#include <cuda_fp16.h>
#include <cstdint>
#include <math.h>

#define EDGES   262144
#define NODES   50000
#define EMB     512
#define KDIM    1536
#define FF      1024
#define NGR     64

#define BM      128            // edges per CTA
#define BN      256            // ff cols per pass
#define BK      32             // K halfs per stage (64 bytes/row)
#define NPASS   8              // 2048 total ff cols / BN
#define KT      48             // K stages per pass (1536/32)
#define G_TOTAL (NPASS * KT)   // 384
#define A_BYTES (BM * BK * 2)  // 8 KB
#define B_BYTES (BN * BK * 2)  // 16 KB
#define STAGE_BYTES (A_BYTES + B_BYTES)
#define NSTAGE  4

__device__ __half g_W1Th[2048 * 1536];                 // W1e|W1f transposed [n][k], fp16
__device__ __half g_xh[(size_t)(NODES + EDGES) * EMB]; // x pre-converted to fp16

__device__ __forceinline__ float gelu_tanh(float x) {
    float inner = fmaf(0.044715f * x * x, x, x);
    float u = 0.7978845608028654f * inner;
    float t; asm("tanh.approx.f32 %0, %1;" : "=f"(t) : "f"(u));
    return 0.5f * x * (1.0f + t);
}
__device__ __forceinline__ void cp16(uint32_t dst, const void* src) {
    asm volatile("cp.async.cg.shared.global [%0], [%1], 16;" :: "r"(dst), "l"(src));
}
#define CP_COMMIT() asm volatile("cp.async.commit_group;" ::: "memory")
#define CP_WAIT2()  asm volatile("cp.async.wait_group 2;" ::: "memory")

__device__ __forceinline__ uint32_t smem_u32(const void* p) {
    uint32_t a;
    asm("{ .reg .u64 t; cvta.to.shared.u64 t, %1; cvt.u32.u64 %0, t; }" : "=r"(a) : "l"(p));
    return a;
}

// m16n8k16 fp16 inputs, f32 accumulate
__device__ __forceinline__ void mma16(float* d, uint32_t a0, uint32_t a1, uint32_t a2,
                                      uint32_t a3, uint32_t b0, uint32_t b1) {
    asm volatile(
        "mma.sync.aligned.m16n8k16.row.col.f32.f16.f16.f32 "
        "{%0,%1,%2,%3},{%4,%5,%6,%7},{%8,%9},{%0,%1,%2,%3};"
        : "+f"(d[0]), "+f"(d[1]), "+f"(d[2]), "+f"(d[3])
        : "r"(a0), "r"(a1), "r"(a2), "r"(a3), "r"(b0), "r"(b1));
}

// Convert x (f32) -> g_xh (fp16). One float4 (4 elems) per thread-iter.
__global__ void cvt_x_kernel(const float* __restrict__ x) {
    const size_t N4 = (size_t)(NODES + EDGES) * EMB / 4;
    size_t i = (size_t)blockIdx.x * blockDim.x + threadIdx.x;
    if (i < N4) {
        float4 f = ((const float4*)x)[i];
        __half2 h0 = __float22half2_rn(make_float2(f.x, f.y));
        __half2 h1 = __float22half2_rn(make_float2(f.z, f.w));
        ((uint2*)g_xh)[i] = make_uint2(*(uint32_t*)&h0, *(uint32_t*)&h1);
    }
}

// Transpose W1e/W1f [1536,1024] -> g_W1Th [2048,1536] (n-major), fp16.
// Also zeroes the output buffer (so ncu launch #5 is the main kernel).
__global__ void transpose_w1(const float* __restrict__ W1e, const float* __restrict__ W1f,
                             float* __restrict__ out, int out_n) {
    __shared__ float t[32][33];
    const float* W = blockIdx.z ? W1f : W1e;
    const int k0 = blockIdx.x * 32, n0 = blockIdx.y * 32;
    const int tx = threadIdx.x, ty0 = threadIdx.y;
    const int tid = ty0 * 32 + tx;
    const int gid = (((int)blockIdx.z * gridDim.y + blockIdx.y) * gridDim.x + blockIdx.x) * 256 + tid;
    if (gid < out_n) out[gid] = 0.0f;
    #pragma unroll
    for (int r = 0; r < 4; r++) {
        int ty = ty0 + r * 8;
        t[ty][tx] = W[(size_t)(k0 + ty) * FF + n0 + tx];
    }
    __syncthreads();
    #pragma unroll
    for (int r = 0; r < 4; r++) {
        int ty = ty0 + r * 8;
        g_W1Th[(size_t)(blockIdx.z * FF + n0 + ty) * KDIM + k0 + tx] =
            __float2half_rn(t[tx][ty]);
    }
}

__global__ __launch_bounds__(256, 1) void fused_edge_mlp_mma(
    const float* __restrict__ pos,
    const float* __restrict__ b1e, const float* __restrict__ W2e, const float* __restrict__ b2e,
    const float* __restrict__ b1f, const float* __restrict__ W2f, const float* __restrict__ b2f,
    const int* __restrict__ batch, const int* __restrict__ edge_index,
    float* __restrict__ out)
{
    extern __shared__ char sm[];
    __shared__ int s_src[BM], s_dst[BM];
    __shared__ float s_accE[BM], s_accF[BM], s_energy[NGR];

    const int tid  = threadIdx.x;
    const int wid  = tid >> 5;
    const int lane = tid & 31;
    const int e0   = blockIdx.x * BM;

    if (tid < BM) {
        s_src[tid] = edge_index[e0 + tid];
        s_dst[tid] = edge_index[EDGES + e0 + tid];
        s_accE[tid] = 0.0f; s_accF[tid] = 0.0f;
    }
    if (tid < NGR) s_energy[tid] = 0.0f;
    __syncthreads();

    // ---- loader assignments: chunk qa (16B = 8 halfs), A rows {r0, r0+64} ----
    const int qa = tid & 3;
    const int r0 = tid >> 2;           // 0..63
    const __half* aS0 = g_xh + (size_t)s_src[r0] * EMB;
    const __half* aD0 = g_xh + (size_t)s_dst[r0] * EMB;
    const __half* aE0 = g_xh + ((size_t)NODES + e0 + r0) * EMB;
    const __half* aS1 = g_xh + (size_t)s_src[r0 + 64] * EMB;
    const __half* aD1 = g_xh + (size_t)s_dst[r0 + 64] * EMB;
    const __half* aE1 = g_xh + ((size_t)NODES + e0 + r0 + 64) * EMB;

    const uint32_t smem_base = smem_u32(sm);

    // stage issue: A[128 x 32h] + B[256 x 32h], 16B cp.async chunks, k-contiguous rows
    auto issue = [&](int g) {
        const int pass = g / KT;
        const int kt   = g - pass * KT;
        const int kpos = kt * BK;                    // half offset in 1536
        const int seg  = kpos >> 9;                  // 0:src 1:dst 2:edge
        const int koff = (kpos & 511) + qa * 8;
        const uint32_t st = smem_base + (g & 3) * STAGE_BYTES;
        const __half* p0 = (seg == 0) ? aS0 : (seg == 1) ? aD0 : aE0;
        const __half* p1 = (seg == 0) ? aS1 : (seg == 1) ? aD1 : aE1;
        cp16(st + (uint32_t)r0 * 64 + qa * 16, p0 + koff);
        cp16(st + (uint32_t)(r0 + 64) * 64 + qa * 16, p1 + koff);
        const __half* wb = g_W1Th + (size_t)(pass * BN) * KDIM + kpos + qa * 8;
        #pragma unroll
        for (int j = 0; j < 4; j++) {
            const int row = r0 + 64 * j;
            cp16(st + A_BYTES + (uint32_t)row * 64 + qa * 16,
                 wb + (size_t)row * KDIM);
        }
        CP_COMMIT();
    };

    issue(0); issue(1); issue(2);

    // ---- warp tiling: 2(M) x 4(N) warps, 64x64 each ----
    const int warp_m = wid & 1;
    const int warp_n = wid >> 1;
    const int lq = lane >> 2;   // 0..7
    const int lc = lane & 3;    // 0..3

    float acc[4][8][4];
    #pragma unroll
    for (int i = 0; i < 4; i++)
        #pragma unroll
        for (int j = 0; j < 8; j++)
            #pragma unroll
            for (int k = 0; k < 4; k++) acc[i][j][k] = 0.0f;

    for (int g = 0; g < G_TOTAL; g++) {
        CP_WAIT2();
        __syncthreads();
        if (g + 3 < G_TOTAL) issue(g + 3);

        const char* st = sm + (g & 3) * STAGE_BYTES;
        const uint4* As = (const uint4*)st;               // [row][4 chunks of 8 halfs]
        const uint4* Bs = (const uint4*)(st + A_BYTES);

        // A fragments: rows (warp_m*64 + mf*16 + lq) and +8; chunk lc = 8 k-halfs
        uint4 a[4][2];
        #pragma unroll
        for (int mf = 0; mf < 4; mf++) {
            const int r = warp_m * 64 + mf * 16 + lq;
            a[mf][0] = As[r * 4 + lc];
            a[mf][1] = As[(r + 8) * 4 + lc];
        }
        #pragma unroll
        for (int nf = 0; nf < 8; nf++) {
            const int c = warp_n * 64 + nf * 8 + lq;
            const uint4 w = Bs[c * 4 + lc];
            #pragma unroll
            for (int mf = 0; mf < 4; mf++) {
                // consistent k-relabeling on A and B sides: 2 MMAs cover the 32-k stage
                mma16(acc[mf][nf], a[mf][0].x, a[mf][1].x, a[mf][0].y, a[mf][1].y, w.x, w.y);
                mma16(acc[mf][nf], a[mf][0].z, a[mf][1].z, a[mf][0].w, a[mf][1].w, w.z, w.w);
            }
        }

        // ---- end-of-pass fused epilogue: bias + gelu + dot(W2), reduce, accumulate ----
        if ((g % KT) == KT - 1) {
            const int pass = g / KT;
            const bool isE = (pass < 4);
            const float* b1 = isE ? b1e : b1f;
            const float* w2 = isE ? W2e : W2f;
            float* sacc = isE ? s_accE : s_accF;
            const int colbase = (pass & 3) * BN + warp_n * 64;
            #pragma unroll
            for (int mf = 0; mf < 4; mf++) {
                float sLo = 0.0f, sHi = 0.0f;
                #pragma unroll
                for (int nf = 0; nf < 8; nf++) {
                    const int c0 = colbase + nf * 8 + 2 * lc;
                    const float2 bb = *(const float2*)&b1[c0];
                    const float2 ww = *(const float2*)&w2[c0];
                    sLo = fmaf(gelu_tanh(acc[mf][nf][0] + bb.x), ww.x, sLo);
                    sLo = fmaf(gelu_tanh(acc[mf][nf][1] + bb.y), ww.y, sLo);
                    sHi = fmaf(gelu_tanh(acc[mf][nf][2] + bb.x), ww.x, sHi);
                    sHi = fmaf(gelu_tanh(acc[mf][nf][3] + bb.y), ww.y, sHi);
                    acc[mf][nf][0] = 0.0f; acc[mf][nf][1] = 0.0f;
                    acc[mf][nf][2] = 0.0f; acc[mf][nf][3] = 0.0f;
                }
                sLo += __shfl_xor_sync(0xffffffffu, sLo, 1);
                sLo += __shfl_xor_sync(0xffffffffu, sLo, 2);
                sHi += __shfl_xor_sync(0xffffffffu, sHi, 1);
                sHi += __shfl_xor_sync(0xffffffffu, sHi, 2);
                if (lc == 0) {
                    const int r = warp_m * 64 + mf * 16 + lq;
                    atomicAdd(&sacc[r], sLo);
                    atomicAdd(&sacc[r + 8], sHi);
                }
            }
        }
    }

    __syncthreads();

    // ---- per-edge readout + scatter ----
    if (tid < BM) {
        const int sN = s_src[tid], dN = s_dst[tid];
        const float Ev = s_accE[tid] + b2e[0];
        const float Fv = s_accF[tid] + b2f[0];
        const float vx = pos[3 * sN + 0] - pos[3 * dN + 0];
        const float vy = pos[3 * sN + 1] - pos[3 * dN + 1];
        const float vz = pos[3 * sN + 2] - pos[3 * dN + 2];
        const float n  = sqrtf(vx * vx + vy * vy + vz * vz);
        const float inv = 1.0f / fmaxf(n, 1e-12f);
        atomicAdd(&s_energy[batch[sN]], Ev);
        float* outF = out + NGR;
        atomicAdd(&outF[3 * sN + 0], Fv * vx * inv);
        atomicAdd(&outF[3 * sN + 1], Fv * vy * inv);
        atomicAdd(&outF[3 * sN + 2], Fv * vz * inv);
    }
    __syncthreads();
    if (tid < NGR) atomicAdd(&out[tid], s_energy[tid]);
}

extern "C" void kernel_launch(void* const* d_in, const int* in_sizes, int n_in,
                              void* d_out, int out_size) {
    const float* x    = (const float*)d_in[0];
    const float* pos  = (const float*)d_in[1];
    const float* W1e  = (const float*)d_in[2];
    const float* b1e  = (const float*)d_in[3];
    const float* W2e  = (const float*)d_in[4];
    const float* b2e  = (const float*)d_in[5];
    const float* W1f  = (const float*)d_in[6];
    const float* b1f  = (const float*)d_in[7];
    const float* W2f  = (const float*)d_in[8];
    const float* b2f  = (const float*)d_in[9];
    const int* batch  = (const int*)d_in[10];
    const int* eidx   = (const int*)d_in[11];
    float* out = (float*)d_out;

    // launch 1: x -> fp16
    const size_t N4 = (size_t)(NODES + EDGES) * EMB / 4;
    cvt_x_kernel<<<(int)((N4 + 255) / 256), 256>>>(x);

    // launch 2: W1 transpose->fp16, fused with output zeroing
    dim3 tg(KDIM / 32, FF / 32, 2);
    transpose_w1<<<tg, dim3(32, 8)>>>(W1e, W1f, out, out_size);

    // launch 3: main fused kernel (ncu -s 5 -c 1 lands here on replay #2)
    const int smem = NSTAGE * STAGE_BYTES;   // 96 KB dynamic
    cudaFuncSetAttribute(fused_edge_mlp_mma, cudaFuncAttributeMaxDynamicSharedMemorySize, smem);
    fused_edge_mlp_mma<<<EDGES / BM, 256, smem>>>(
        pos, b1e, W2e, b2e, b1f, W2f, b2f, batch, eidx, out);
}

// round 5
// speedup vs baseline: 10.4569x; 1.8258x over previous
#include <cuda_runtime.h>
#include <cuda_fp16.h>
#include <cstdint>
#include <math.h>

#define EDGES   262144
#define NODES   50000
#define EMB     512
#define FF      1024
#define NGR     64

__device__ __half g_xh[(size_t)(NODES + EDGES) * EMB];  // x in fp16
__device__ __half g_WnT[4096 * 512];   // node-GEMM weights, n-major: [Esrc|Fsrc|Edst|Fdst]
__device__ __half g_WeT[2048 * 512];   // edge-token weights, n-major: [Eedge|Fedge]
__device__ __half g_P[(size_t)NODES * 4096];  // precomputed node contributions

__device__ __forceinline__ float gelu_tanh(float x) {
    float inner = fmaf(0.044715f * x * x, x, x);
    float u = 0.7978845608028654f * inner;
    float t; asm("tanh.approx.f32 %0, %1;" : "=f"(t) : "f"(u));
    return 0.5f * x * (1.0f + t);
}
__device__ __forceinline__ void cp16(uint32_t dst, const void* src) {
    asm volatile("cp.async.cg.shared.global [%0], [%1], 16;" :: "r"(dst), "l"(src));
}
#define CP_COMMIT() asm volatile("cp.async.commit_group;" ::: "memory")
#define CP_WAIT2()  asm volatile("cp.async.wait_group 2;" ::: "memory")

__device__ __forceinline__ uint32_t smem_u32(const void* p) {
    uint32_t a;
    asm("{ .reg .u64 t; cvta.to.shared.u64 t, %1; cvt.u32.u64 %0, t; }" : "=r"(a) : "l"(p));
    return a;
}
__device__ __forceinline__ void mma16(float* d, uint32_t a0, uint32_t a1, uint32_t a2,
                                      uint32_t a3, uint32_t b0, uint32_t b1) {
    asm volatile(
        "mma.sync.aligned.m16n8k16.row.col.f32.f16.f16.f32 "
        "{%0,%1,%2,%3},{%4,%5,%6,%7},{%8,%9},{%0,%1,%2,%3};"
        : "+f"(d[0]), "+f"(d[1]), "+f"(d[2]), "+f"(d[3])
        : "r"(a0), "r"(a1), "r"(a2), "r"(a3), "r"(b0), "r"(b1));
}

// ---------------- prep kernels ----------------

__global__ void cvt_x_kernel(const float* __restrict__ x) {
    const size_t N4 = (size_t)(NODES + EDGES) * EMB / 4;
    size_t i = (size_t)blockIdx.x * blockDim.x + threadIdx.x;
    if (i < N4) {
        float4 f = ((const float4*)x)[i];
        __half2 h0 = __float22half2_rn(make_float2(f.x, f.y));
        __half2 h1 = __float22half2_rn(make_float2(f.z, f.w));
        ((uint2*)g_xh)[i] = make_uint2(*(uint32_t*)&h0, *(uint32_t*)&h1);
    }
}

// Build g_WnT (4096 n-rows) and g_WeT (2048 n-rows) from W1e/W1f; also zero out[].
// n-block order: 0:E-src 1:F-src 2:E-dst 3:F-dst 4:E-edge 5:F-edge
__global__ void prep_w1(const float* __restrict__ W1e, const float* __restrict__ W1f,
                        float* __restrict__ out, int out_n) {
    __shared__ float t[32][33];
    const int k0 = blockIdx.x * 32;        // 0..480
    const int n0 = blockIdx.y * 32;        // 0..6112
    const int tx = threadIdx.x, ty0 = threadIdx.y;
    const int tid = ty0 * 32 + tx;
    const int gid = ((int)blockIdx.y * gridDim.x + blockIdx.x) * 256 + tid;
    if (gid < out_n) out[gid] = 0.0f;

    const int nblk = n0 >> 10;
    const float* W = (nblk & 1) ? W1f : W1e;
    const int krow = (nblk >> 1) * 512;
    const int ncol = n0 & 1023;
    #pragma unroll
    for (int r = 0; r < 4; r++) {
        int ty = ty0 + r * 8;
        t[ty][tx] = W[(size_t)(krow + k0 + ty) * FF + ncol + tx];
    }
    __syncthreads();
    #pragma unroll
    for (int r = 0; r < 4; r++) {
        int ty = ty0 + r * 8;
        __half v = __float2half_rn(t[tx][ty]);
        int n = n0 + ty, k = k0 + tx;
        if (n < 4096) g_WnT[(size_t)n * 512 + k] = v;
        else          g_WeT[(size_t)(n - 4096) * 512 + k] = v;
    }
}

// ---------------- node GEMM: g_P = x_nodes @ WnT^T  (M=50000,N=4096,K=512) ----------------

#define NG_A (128 * 32 * 2)   // 8 KB
#define NG_B (256 * 32 * 2)   // 16 KB
#define NG_ST (NG_A + NG_B)

__global__ __launch_bounds__(256, 1) void node_gemm() {
    extern __shared__ char sm[];
    const int tid = threadIdx.x, wid = tid >> 5, lane = tid & 31;
    const int m0 = blockIdx.x * 128, n0 = blockIdx.y * 256;
    const uint32_t sb = smem_u32(sm);

    const int qa = tid & 3, r0 = tid >> 2;

    auto issue = [&](int kt) {
        const uint32_t st = sb + (kt & 3) * NG_ST;
        const int ko = kt * 32 + qa * 8;
        int g0 = m0 + r0;       if (g0 >= NODES) g0 = 0;
        int g1 = m0 + r0 + 64;  if (g1 >= NODES) g1 = 0;
        cp16(st + (uint32_t)r0 * 64 + qa * 16, g_xh + (size_t)g0 * 512 + ko);
        cp16(st + (uint32_t)(r0 + 64) * 64 + qa * 16, g_xh + (size_t)g1 * 512 + ko);
        #pragma unroll
        for (int j = 0; j < 4; j++) {
            const int row = r0 + 64 * j;
            cp16(st + NG_A + (uint32_t)row * 64 + qa * 16,
                 g_WnT + (size_t)(n0 + row) * 512 + ko);
        }
        CP_COMMIT();
    };
    issue(0); issue(1); issue(2);

    const int warp_m = wid & 1, warp_n = wid >> 1;
    const int lq = lane >> 2, lc = lane & 3;

    float acc[4][8][4];
    #pragma unroll
    for (int i = 0; i < 4; i++)
        #pragma unroll
        for (int j = 0; j < 8; j++)
            #pragma unroll
            for (int k = 0; k < 4; k++) acc[i][j][k] = 0.0f;

    for (int kt = 0; kt < 16; kt++) {
        CP_WAIT2();
        __syncthreads();
        if (kt + 3 < 16) issue(kt + 3);
        const char* st = sm + (kt & 3) * NG_ST;
        const uint4* As = (const uint4*)st;
        const uint4* Bs = (const uint4*)(st + NG_A);
        uint4 a[4][2];
        #pragma unroll
        for (int mf = 0; mf < 4; mf++) {
            const int r = warp_m * 64 + mf * 16 + lq;
            a[mf][0] = As[r * 4 + lc];
            a[mf][1] = As[(r + 8) * 4 + lc];
        }
        #pragma unroll
        for (int nf = 0; nf < 8; nf++) {
            const int c = warp_n * 64 + nf * 8 + lq;
            const uint4 w = Bs[c * 4 + lc];
            #pragma unroll
            for (int mf = 0; mf < 4; mf++) {
                mma16(acc[mf][nf], a[mf][0].x, a[mf][1].x, a[mf][0].y, a[mf][1].y, w.x, w.y);
                mma16(acc[mf][nf], a[mf][0].z, a[mf][1].z, a[mf][0].w, a[mf][1].w, w.z, w.w);
            }
        }
    }

    #pragma unroll
    for (int mf = 0; mf < 4; mf++) {
        const int r = m0 + warp_m * 64 + mf * 16 + lq;
        #pragma unroll
        for (int nf = 0; nf < 8; nf++) {
            const int c = n0 + warp_n * 64 + nf * 8 + 2 * lc;
            if (r < NODES) {
                __half2 h = __float22half2_rn(make_float2(acc[mf][nf][0], acc[mf][nf][1]));
                *(__half2*)&g_P[(size_t)r * 4096 + c] = h;
            }
            if (r + 8 < NODES) {
                __half2 h = __float22half2_rn(make_float2(acc[mf][nf][2], acc[mf][nf][3]));
                *(__half2*)&g_P[(size_t)(r + 8) * 4096 + c] = h;
            }
        }
    }
}

// ---------------- fused edge kernel: K=512 GEMM + P/Q gather + gelu·W2 + scatter ----------------

#define FB_ST 16384          // B stage bytes (256 rows x 64 B)
#define FB_OFF 131072        // B region after 128 KB resident A

__global__ __launch_bounds__(256, 1) void fused_edge(
    const float* __restrict__ pos,
    const float* __restrict__ b1e, const float* __restrict__ W2e, const float* __restrict__ b2e,
    const float* __restrict__ b1f, const float* __restrict__ W2f, const float* __restrict__ b2f,
    const int* __restrict__ batch, const int* __restrict__ edge_index,
    float* __restrict__ out)
{
    extern __shared__ char sm[];
    __shared__ int s_src[128], s_dst[128];
    __shared__ float s_accE[128], s_accF[128], s_energy[NGR];

    const int tid = threadIdx.x, wid = tid >> 5, lane = tid & 31;
    const int e0 = blockIdx.x * 128;
    const uint32_t sb = smem_u32(sm);

    if (tid < 128) {
        s_src[tid] = edge_index[e0 + tid];
        s_dst[tid] = edge_index[EDGES + e0 + tid];
        s_accE[tid] = 0.0f; s_accF[tid] = 0.0f;
    }
    if (tid < NGR) s_energy[tid] = 0.0f;
    __syncthreads();

    // ---- resident A: 128 edge-token rows x 512 halfs, parity-XOR chunk swizzle ----
    {
        const int qa8 = tid & 7, rr = tid >> 3;   // 8 chunk-lanes, 32 row-lanes
        #pragma unroll
        for (int j = 0; j < 4; j++) {
            const int row = rr + 32 * j;
            const size_t src = (size_t)(NODES + e0 + row) * 512;
            const uint32_t drow = sb + (uint32_t)row * 1024;
            const uint32_t sw = (row & 1) * 4;
            #pragma unroll
            for (int cc = 0; cc < 8; cc++) {
                const int chunk = qa8 + 8 * cc;
                cp16(drow + (uint32_t)((chunk ^ sw) * 16), g_xh + src + chunk * 8);
            }
        }
        CP_COMMIT();
    }

    // ---- B stage loader: 256 rows x 32 halfs ----
    const int qa = tid & 3, r0 = tid >> 2;
    auto issueB = [&](int g) {
        const int pass = g >> 4, kt = g & 15;
        const uint32_t st = sb + FB_OFF + (g & 3) * FB_ST;
        const int ko = kt * 32 + qa * 8;
        #pragma unroll
        for (int j = 0; j < 4; j++) {
            const int row = r0 + 64 * j;
            cp16(st + (uint32_t)row * 64 + qa * 16,
                 g_WeT + (size_t)(pass * 256 + row) * 512 + ko);
        }
        CP_COMMIT();
    };
    issueB(0); issueB(1); issueB(2);

    const int warp_m = wid & 1, warp_n = wid >> 1;
    const int lq = lane >> 2, lc = lane & 3;
    const uint32_t asw = (lq & 1) * 4;   // A slot swizzle (row parity == lq parity)

    float acc[4][8][4];
    #pragma unroll
    for (int i = 0; i < 4; i++)
        #pragma unroll
        for (int j = 0; j < 8; j++)
            #pragma unroll
            for (int k = 0; k < 4; k++) acc[i][j][k] = 0.0f;

    const uint4* Ares = (const uint4*)sm;   // [128 rows][64 slots]

    for (int g = 0; g < 128; g++) {
        CP_WAIT2();
        __syncthreads();
        if (g + 3 < 128) issueB(g + 3);

        const int kt = g & 15;
        const uint4* Bs = (const uint4*)(sm + FB_OFF + (g & 3) * FB_ST);
        const int slot = (kt * 4 + lc) ^ asw;

        uint4 a[4][2];
        #pragma unroll
        for (int mf = 0; mf < 4; mf++) {
            const int r = warp_m * 64 + mf * 16 + lq;
            a[mf][0] = Ares[r * 64 + slot];
            a[mf][1] = Ares[(r + 8) * 64 + slot];
        }
        #pragma unroll
        for (int nf = 0; nf < 8; nf++) {
            const int c = warp_n * 64 + nf * 8 + lq;
            const uint4 w = Bs[c * 4 + lc];
            #pragma unroll
            for (int mf = 0; mf < 4; mf++) {
                mma16(acc[mf][nf], a[mf][0].x, a[mf][1].x, a[mf][0].y, a[mf][1].y, w.x, w.y);
                mma16(acc[mf][nf], a[mf][0].z, a[mf][1].z, a[mf][0].w, a[mf][1].w, w.z, w.w);
            }
        }

        // ---- end-of-pass: add gathered P[src]/P[dst], bias, gelu, dot W2 ----
        if (kt == 15) {
            const int pass = g >> 4;
            const bool isE = (pass < 4);
            const float* b1 = isE ? b1e : b1f;
            const float* w2 = isE ? W2e : W2f;
            float* sacc = isE ? s_accE : s_accF;
            const int colbase = (pass & 3) * 256 + warp_n * 64;   // within 1024-col E/F block
            const int pS = isE ? 0 : 1024;
            const int pD = isE ? 2048 : 3072;
            #pragma unroll
            for (int mf = 0; mf < 4; mf++) {
                const int r = warp_m * 64 + mf * 16 + lq;
                const __half* PsL = g_P + (size_t)s_src[r] * 4096 + pS + colbase;
                const __half* PdL = g_P + (size_t)s_dst[r] * 4096 + pD + colbase;
                const __half* PsH = g_P + (size_t)s_src[r + 8] * 4096 + pS + colbase;
                const __half* PdH = g_P + (size_t)s_dst[r + 8] * 4096 + pD + colbase;
                float sLo = 0.0f, sHi = 0.0f;
                #pragma unroll
                for (int nf = 0; nf < 8; nf++) {
                    const int cc = nf * 8 + 2 * lc;
                    const float2 bb = *(const float2*)&b1[colbase + cc];
                    const float2 ww = *(const float2*)&w2[colbase + cc];
                    const float2 ps0 = __half22float2(*(const __half2*)(PsL + cc));
                    const float2 pd0 = __half22float2(*(const __half2*)(PdL + cc));
                    const float2 ps1 = __half22float2(*(const __half2*)(PsH + cc));
                    const float2 pd1 = __half22float2(*(const __half2*)(PdH + cc));
                    sLo = fmaf(gelu_tanh(acc[mf][nf][0] + ps0.x + pd0.x + bb.x), ww.x, sLo);
                    sLo = fmaf(gelu_tanh(acc[mf][nf][1] + ps0.y + pd0.y + bb.y), ww.y, sLo);
                    sHi = fmaf(gelu_tanh(acc[mf][nf][2] + ps1.x + pd1.x + bb.x), ww.x, sHi);
                    sHi = fmaf(gelu_tanh(acc[mf][nf][3] + ps1.y + pd1.y + bb.y), ww.y, sHi);
                    acc[mf][nf][0] = 0.0f; acc[mf][nf][1] = 0.0f;
                    acc[mf][nf][2] = 0.0f; acc[mf][nf][3] = 0.0f;
                }
                sLo += __shfl_xor_sync(0xffffffffu, sLo, 1);
                sLo += __shfl_xor_sync(0xffffffffu, sLo, 2);
                sHi += __shfl_xor_sync(0xffffffffu, sHi, 1);
                sHi += __shfl_xor_sync(0xffffffffu, sHi, 2);
                if (lc == 0) {
                    atomicAdd(&sacc[r], sLo);
                    atomicAdd(&sacc[r + 8], sHi);
                }
            }
        }
    }

    __syncthreads();

    if (tid < 128) {
        const int sN = s_src[tid], dN = s_dst[tid];
        const float Ev = s_accE[tid] + b2e[0];
        const float Fv = s_accF[tid] + b2f[0];
        const float vx = pos[3 * sN + 0] - pos[3 * dN + 0];
        const float vy = pos[3 * sN + 1] - pos[3 * dN + 1];
        const float vz = pos[3 * sN + 2] - pos[3 * dN + 2];
        const float n  = sqrtf(vx * vx + vy * vy + vz * vz);
        const float inv = 1.0f / fmaxf(n, 1e-12f);
        atomicAdd(&s_energy[batch[sN]], Ev);
        float* outF = out + NGR;
        atomicAdd(&outF[3 * sN + 0], Fv * vx * inv);
        atomicAdd(&outF[3 * sN + 1], Fv * vy * inv);
        atomicAdd(&outF[3 * sN + 2], Fv * vz * inv);
    }
    __syncthreads();
    if (tid < NGR) atomicAdd(&out[tid], s_energy[tid]);
}

extern "C" void kernel_launch(void* const* d_in, const int* in_sizes, int n_in,
                              void* d_out, int out_size) {
    const float* x    = (const float*)d_in[0];
    const float* pos  = (const float*)d_in[1];
    const float* W1e  = (const float*)d_in[2];
    const float* b1e  = (const float*)d_in[3];
    const float* W2e  = (const float*)d_in[4];
    const float* b2e  = (const float*)d_in[5];
    const float* W1f  = (const float*)d_in[6];
    const float* b1f  = (const float*)d_in[7];
    const float* W2f  = (const float*)d_in[8];
    const float* b2f  = (const float*)d_in[9];
    const int* batch  = (const int*)d_in[10];
    const int* eidx   = (const int*)d_in[11];
    float* out = (float*)d_out;

    const size_t N4 = (size_t)(NODES + EDGES) * EMB / 4;
    cvt_x_kernel<<<(int)((N4 + 255) / 256), 256>>>(x);

    prep_w1<<<dim3(16, 192), dim3(32, 8)>>>(W1e, W1f, out, out_size);

    const int ng_smem = 4 * NG_ST;  // 96 KB
    cudaFuncSetAttribute(node_gemm, cudaFuncAttributeMaxDynamicSharedMemorySize, ng_smem);
    node_gemm<<<dim3((NODES + 127) / 128, 16), 256, ng_smem>>>();

    const int fe_smem = FB_OFF + 4 * FB_ST;  // 128 KB A + 64 KB B = 192 KB
    cudaFuncSetAttribute(fused_edge, cudaFuncAttributeMaxDynamicSharedMemorySize, fe_smem);
    fused_edge<<<EDGES / 128, 256, fe_smem>>>(
        pos, b1e, W2e, b2e, b1f, W2f, b2f, batch, eidx, out);
}

// round 6
// speedup vs baseline: 12.2935x; 1.1756x over previous
#include <cuda_runtime.h>
#include <cuda_fp16.h>
#include <cstdint>
#include <math.h>

#define EDGES   262144
#define NODES   50000
#define EMB     512
#define FF      1024
#define NGR     64

__device__ __half g_xh[(size_t)(NODES + EDGES) * EMB];  // x in fp16
__device__ __half g_WnT[4096 * 512];   // node weights n-major: [Esrc|Fsrc|Edst|Fdst]
__device__ __half g_WeT[2048 * 512];   // edge-token weights n-major: [Eedge|Fedge]
__device__ __half g_P[(size_t)NODES * 4096];  // precomputed node contributions

__device__ __forceinline__ float gelu_tanh(float x) {
    float inner = fmaf(0.044715f * x * x, x, x);
    float u = 0.7978845608028654f * inner;
    float t; asm("tanh.approx.f32 %0, %1;" : "=f"(t) : "f"(u));
    return 0.5f * x * (1.0f + t);
}
__device__ __forceinline__ void cp16(uint32_t dst, const void* src) {
    asm volatile("cp.async.cg.shared.global [%0], [%1], 16;" :: "r"(dst), "l"(src));
}
#define CP_COMMIT() asm volatile("cp.async.commit_group;" ::: "memory")
#define CP_WAIT2()  asm volatile("cp.async.wait_group 2;" ::: "memory")

__device__ __forceinline__ uint32_t smem_u32(const void* p) {
    uint32_t a;
    asm("{ .reg .u64 t; cvta.to.shared.u64 t, %1; cvt.u32.u64 %0, t; }" : "=r"(a) : "l"(p));
    return a;
}
__device__ __forceinline__ void mma16(float* d, uint32_t a0, uint32_t a1, uint32_t a2,
                                      uint32_t a3, uint32_t b0, uint32_t b1) {
    asm volatile(
        "mma.sync.aligned.m16n8k16.row.col.f32.f16.f16.f32 "
        "{%0,%1,%2,%3},{%4,%5,%6,%7},{%8,%9},{%0,%1,%2,%3};"
        : "+f"(d[0]), "+f"(d[1]), "+f"(d[2]), "+f"(d[3])
        : "r"(a0), "r"(a1), "r"(a2), "r"(a3), "r"(b0), "r"(b1));
}
__device__ __forceinline__ void ldsm4(uint32_t* r, uint32_t addr) {
    asm volatile("ldmatrix.sync.aligned.m8n8.x4.shared.b16 {%0,%1,%2,%3}, [%4];"
        : "=r"(r[0]), "=r"(r[1]), "=r"(r[2]), "=r"(r[3]) : "r"(addr));
}

// ---------------- prep kernels ----------------

__global__ void cvt_x_kernel(const float* __restrict__ x) {
    const size_t N4 = (size_t)(NODES + EDGES) * EMB / 4;
    size_t i = (size_t)blockIdx.x * blockDim.x + threadIdx.x;
    if (i < N4) {
        float4 f = ((const float4*)x)[i];
        __half2 h0 = __float22half2_rn(make_float2(f.x, f.y));
        __half2 h1 = __float22half2_rn(make_float2(f.z, f.w));
        ((uint2*)g_xh)[i] = make_uint2(*(uint32_t*)&h0, *(uint32_t*)&h1);
    }
}

// Build g_WnT / g_WeT from W1e/W1f; also zero out[].
__global__ void prep_w1(const float* __restrict__ W1e, const float* __restrict__ W1f,
                        float* __restrict__ out, int out_n) {
    __shared__ float t[32][33];
    const int k0 = blockIdx.x * 32;
    const int n0 = blockIdx.y * 32;
    const int tx = threadIdx.x, ty0 = threadIdx.y;
    const int tid = ty0 * 32 + tx;
    const int gid = ((int)blockIdx.y * gridDim.x + blockIdx.x) * 256 + tid;
    if (gid < out_n) out[gid] = 0.0f;

    const int nblk = n0 >> 10;                 // 0:Esrc 1:Fsrc 2:Edst 3:Fdst 4:Eedge 5:Fedge
    const float* W = (nblk & 1) ? W1f : W1e;
    const int krow = (nblk >> 1) * 512;
    const int ncol = n0 & 1023;
    #pragma unroll
    for (int r = 0; r < 4; r++) {
        int ty = ty0 + r * 8;
        t[ty][tx] = W[(size_t)(krow + k0 + ty) * FF + ncol + tx];
    }
    __syncthreads();
    #pragma unroll
    for (int r = 0; r < 4; r++) {
        int ty = ty0 + r * 8;
        __half v = __float2half_rn(t[tx][ty]);
        int n = n0 + ty, k = k0 + tx;
        if (n < 4096) g_WnT[(size_t)n * 512 + k] = v;
        else          g_WeT[(size_t)(n - 4096) * 512 + k] = v;
    }
}

// ---------------- node GEMM: g_P = x_nodes @ WnT^T  (M=50000,N=4096,K=512) ----------------
// BK=64 (128B rows), Swizzle<3,4,3>: chunk16 q stored at (q ^ (row&7)).

#define NG_A 16384
#define NG_B 32768
#define NG_ST (NG_A + NG_B)

__global__ __launch_bounds__(256, 1) void node_gemm() {
    extern __shared__ char sm[];
    const int tid = threadIdx.x, wid = tid >> 5, lane = tid & 31;
    const int m0 = blockIdx.x * 128, n0 = blockIdx.y * 256;
    const uint32_t sb = smem_u32(sm);

    auto issue = [&](int kt) {
        const uint32_t st = sb + (kt & 3) * NG_ST;
        const int ko = kt * 64;
        #pragma unroll
        for (int j = 0; j < 4; j++) {                 // A: 128 rows x 8 chunks
            const int cid = j * 256 + tid;
            const int row = cid >> 3, q = cid & 7;
            int grow = m0 + row; if (grow >= NODES) grow = 0;
            cp16(st + (uint32_t)row * 128 + (uint32_t)((q ^ (row & 7)) << 4),
                 g_xh + (size_t)grow * 512 + ko + q * 8);
        }
        #pragma unroll
        for (int j = 0; j < 8; j++) {                 // B: 256 rows x 8 chunks
            const int cid = j * 256 + tid;
            const int row = cid >> 3, q = cid & 7;
            cp16(st + NG_A + (uint32_t)row * 128 + (uint32_t)((q ^ (row & 7)) << 4),
                 g_WnT + (size_t)(n0 + row) * 512 + ko + q * 8);
        }
        CP_COMMIT();
    };
    issue(0); issue(1); issue(2);

    const int warp_m = wid & 1, warp_n = wid >> 1;
    const int lq = lane >> 2, lc = lane & 3;
    // ldmatrix per-lane addressing constants
    const int arow = warp_m * 64 + (lane & 7) + ((lane >> 3) & 1) * 8;
    const int acs  = (lane >> 4) & 1;
    const int aswz = arow & 7;
    const int brow = warp_n * 64 + ((lane >> 4) & 1) * 8 + (lane & 7);
    const int bcs  = (lane >> 3) & 1;
    const int bswz = brow & 7;

    float acc[4][8][4];
    #pragma unroll
    for (int i = 0; i < 4; i++)
        #pragma unroll
        for (int j = 0; j < 8; j++)
            #pragma unroll
            for (int k = 0; k < 4; k++) acc[i][j][k] = 0.0f;

    for (int kt = 0; kt < 8; kt++) {
        CP_WAIT2();
        __syncthreads();
        if (kt + 3 < 8) issue(kt + 3);
        const uint32_t Ab = sb + (kt & 3) * NG_ST;
        const uint32_t Bb = Ab + NG_A;
        #pragma unroll
        for (int c = 0; c < 4; c++) {
            uint32_t a[4][4], b[8][2];
            #pragma unroll
            for (int mf = 0; mf < 4; mf++)
                ldsm4(a[mf], Ab + (uint32_t)(arow + 16 * mf) * 128 +
                             (uint32_t)(((2 * c + acs) ^ aswz) << 4));
            #pragma unroll
            for (int p = 0; p < 4; p++) {
                uint32_t r[4];
                ldsm4(r, Bb + (uint32_t)(brow + 16 * p) * 128 +
                         (uint32_t)(((2 * c + bcs) ^ bswz) << 4));
                b[2 * p][0] = r[0]; b[2 * p][1] = r[1];
                b[2 * p + 1][0] = r[2]; b[2 * p + 1][1] = r[3];
            }
            #pragma unroll
            for (int nf = 0; nf < 8; nf++)
                #pragma unroll
                for (int mf = 0; mf < 4; mf++)
                    mma16(acc[mf][nf], a[mf][0], a[mf][1], a[mf][2], a[mf][3],
                          b[nf][0], b[nf][1]);
        }
    }

    #pragma unroll
    for (int mf = 0; mf < 4; mf++) {
        const int r = m0 + warp_m * 64 + mf * 16 + lq;
        #pragma unroll
        for (int nf = 0; nf < 8; nf++) {
            const int c = n0 + warp_n * 64 + nf * 8 + 2 * lc;
            if (r < NODES) {
                __half2 h = __float22half2_rn(make_float2(acc[mf][nf][0], acc[mf][nf][1]));
                *(__half2*)&g_P[(size_t)r * 4096 + c] = h;
            }
            if (r + 8 < NODES) {
                __half2 h = __float22half2_rn(make_float2(acc[mf][nf][2], acc[mf][nf][3]));
                *(__half2*)&g_P[(size_t)(r + 8) * 4096 + c] = h;
            }
        }
    }
}

// ---------------- fused edge kernel ----------------
// Resident A: 8 k64 sub-tiles (128 rows x 128B each, swizzled) = 128 KB.
// B ring: 3 stages x 32 KB at FB_OFF.

#define FB_OFF 131072
#define FB_ST  32768

__global__ __launch_bounds__(256, 1) void fused_edge(
    const float* __restrict__ pos,
    const float* __restrict__ b1e, const float* __restrict__ W2e, const float* __restrict__ b2e,
    const float* __restrict__ b1f, const float* __restrict__ W2f, const float* __restrict__ b2f,
    const int* __restrict__ batch, const int* __restrict__ edge_index,
    float* __restrict__ out)
{
    extern __shared__ char sm[];
    __shared__ int s_src[128], s_dst[128];
    __shared__ float s_accE[128], s_accF[128], s_energy[NGR];

    const int tid = threadIdx.x, wid = tid >> 5, lane = tid & 31;
    const int e0 = blockIdx.x * 128;
    const uint32_t sb = smem_u32(sm);

    if (tid < 128) {
        s_src[tid] = edge_index[e0 + tid];
        s_dst[tid] = edge_index[EDGES + e0 + tid];
        s_accE[tid] = 0.0f; s_accF[tid] = 0.0f;
    }
    if (tid < NGR) s_energy[tid] = 0.0f;

    // resident A: 8192 chunks of 16B, 32 per thread (single commit group)
    #pragma unroll
    for (int j = 0; j < 32; j++) {
        const int cid = j * 256 + tid;
        const int t = cid >> 10, row = (cid >> 3) & 127, q = cid & 7;
        cp16(sb + (uint32_t)t * 16384 + (uint32_t)row * 128 +
                 (uint32_t)((q ^ (row & 7)) << 4),
             g_xh + ((size_t)(NODES + e0 + row)) * 512 + t * 64 + q * 8);
    }
    CP_COMMIT();

    auto issueB = [&](int g, int slot) {
        const int pass = g >> 3, kt = g & 7;
        const uint32_t st = sb + FB_OFF + (uint32_t)slot * FB_ST;
        #pragma unroll
        for (int j = 0; j < 8; j++) {
            const int cid = j * 256 + tid;
            const int row = cid >> 3, q = cid & 7;
            cp16(st + (uint32_t)row * 128 + (uint32_t)((q ^ (row & 7)) << 4),
                 g_WeT + (size_t)(pass * 256 + row) * 512 + kt * 64 + q * 8);
        }
        CP_COMMIT();
    };
    issueB(0, 0); issueB(1, 1);
    __syncthreads();   // also covers s_src/s_dst visibility

    const int warp_m = wid & 1, warp_n = wid >> 1;
    const int lq = lane >> 2, lc = lane & 3;
    const int arow = warp_m * 64 + (lane & 7) + ((lane >> 3) & 1) * 8;
    const int acs  = (lane >> 4) & 1;
    const int aswz = arow & 7;
    const int brow = warp_n * 64 + ((lane >> 4) & 1) * 8 + (lane & 7);
    const int bcs  = (lane >> 3) & 1;
    const int bswz = brow & 7;

    float acc[4][8][4];
    #pragma unroll
    for (int i = 0; i < 4; i++)
        #pragma unroll
        for (int j = 0; j < 8; j++)
            #pragma unroll
            for (int k = 0; k < 4; k++) acc[i][j][k] = 0.0f;

    int slot = 0;  // stage being consumed
    for (int g = 0; g < 64; g++) {
        CP_WAIT2();
        __syncthreads();
        if (g + 2 < 64) issueB(g + 2, (slot + 2) % 3);

        const int kt = g & 7;
        const uint32_t Ab = sb + (uint32_t)kt * 16384;
        const uint32_t Bb = sb + FB_OFF + (uint32_t)slot * FB_ST;
        slot = (slot + 1) % 3;

        #pragma unroll
        for (int c = 0; c < 4; c++) {
            uint32_t a[4][4], b[8][2];
            #pragma unroll
            for (int mf = 0; mf < 4; mf++)
                ldsm4(a[mf], Ab + (uint32_t)(arow + 16 * mf) * 128 +
                             (uint32_t)(((2 * c + acs) ^ aswz) << 4));
            #pragma unroll
            for (int p = 0; p < 4; p++) {
                uint32_t r[4];
                ldsm4(r, Bb + (uint32_t)(brow + 16 * p) * 128 +
                         (uint32_t)(((2 * c + bcs) ^ bswz) << 4));
                b[2 * p][0] = r[0]; b[2 * p][1] = r[1];
                b[2 * p + 1][0] = r[2]; b[2 * p + 1][1] = r[3];
            }
            #pragma unroll
            for (int nf = 0; nf < 8; nf++)
                #pragma unroll
                for (int mf = 0; mf < 4; mf++)
                    mma16(acc[mf][nf], a[mf][0], a[mf][1], a[mf][2], a[mf][3],
                          b[nf][0], b[nf][1]);
        }

        // ---- end-of-pass: add gathered P[src]/P[dst], bias, gelu, dot W2 ----
        if (kt == 7) {
            const int pass = g >> 3;
            const bool isE = (pass < 4);
            const float* b1 = isE ? b1e : b1f;
            const float* w2 = isE ? W2e : W2f;
            float* sacc = isE ? s_accE : s_accF;
            const int colbase = (pass & 3) * 256 + warp_n * 64;
            const int pS = isE ? 0 : 1024;
            const int pD = isE ? 2048 : 3072;
            #pragma unroll
            for (int mf = 0; mf < 4; mf++) {
                const int r = warp_m * 64 + mf * 16 + lq;
                const __half* PsL = g_P + (size_t)s_src[r] * 4096 + pS + colbase;
                const __half* PdL = g_P + (size_t)s_dst[r] * 4096 + pD + colbase;
                const __half* PsH = g_P + (size_t)s_src[r + 8] * 4096 + pS + colbase;
                const __half* PdH = g_P + (size_t)s_dst[r + 8] * 4096 + pD + colbase;
                float sLo = 0.0f, sHi = 0.0f;
                #pragma unroll
                for (int nf = 0; nf < 8; nf++) {
                    const int cc = nf * 8 + 2 * lc;
                    const float2 bb = *(const float2*)&b1[colbase + cc];
                    const float2 ww = *(const float2*)&w2[colbase + cc];
                    const float2 ps0 = __half22float2(*(const __half2*)(PsL + cc));
                    const float2 pd0 = __half22float2(*(const __half2*)(PdL + cc));
                    const float2 ps1 = __half22float2(*(const __half2*)(PsH + cc));
                    const float2 pd1 = __half22float2(*(const __half2*)(PdH + cc));
                    sLo = fmaf(gelu_tanh(acc[mf][nf][0] + ps0.x + pd0.x + bb.x), ww.x, sLo);
                    sLo = fmaf(gelu_tanh(acc[mf][nf][1] + ps0.y + pd0.y + bb.y), ww.y, sLo);
                    sHi = fmaf(gelu_tanh(acc[mf][nf][2] + ps1.x + pd1.x + bb.x), ww.x, sHi);
                    sHi = fmaf(gelu_tanh(acc[mf][nf][3] + ps1.y + pd1.y + bb.y), ww.y, sHi);
                    acc[mf][nf][0] = 0.0f; acc[mf][nf][1] = 0.0f;
                    acc[mf][nf][2] = 0.0f; acc[mf][nf][3] = 0.0f;
                }
                sLo += __shfl_xor_sync(0xffffffffu, sLo, 1);
                sLo += __shfl_xor_sync(0xffffffffu, sLo, 2);
                sHi += __shfl_xor_sync(0xffffffffu, sHi, 1);
                sHi += __shfl_xor_sync(0xffffffffu, sHi, 2);
                if (lc == 0) {
                    atomicAdd(&sacc[r], sLo);
                    atomicAdd(&sacc[r + 8], sHi);
                }
            }
        }
    }

    __syncthreads();

    if (tid < 128) {
        const int sN = s_src[tid], dN = s_dst[tid];
        const float Ev = s_accE[tid] + b2e[0];
        const float Fv = s_accF[tid] + b2f[0];
        const float vx = pos[3 * sN + 0] - pos[3 * dN + 0];
        const float vy = pos[3 * sN + 1] - pos[3 * dN + 1];
        const float vz = pos[3 * sN + 2] - pos[3 * dN + 2];
        const float n  = sqrtf(vx * vx + vy * vy + vz * vz);
        const float inv = 1.0f / fmaxf(n, 1e-12f);
        atomicAdd(&s_energy[batch[sN]], Ev);
        float* outF = out + NGR;
        atomicAdd(&outF[3 * sN + 0], Fv * vx * inv);
        atomicAdd(&outF[3 * sN + 1], Fv * vy * inv);
        atomicAdd(&outF[3 * sN + 2], Fv * vz * inv);
    }
    __syncthreads();
    if (tid < NGR) atomicAdd(&out[tid], s_energy[tid]);
}

extern "C" void kernel_launch(void* const* d_in, const int* in_sizes, int n_in,
                              void* d_out, int out_size) {
    const float* x    = (const float*)d_in[0];
    const float* pos  = (const float*)d_in[1];
    const float* W1e  = (const float*)d_in[2];
    const float* b1e  = (const float*)d_in[3];
    const float* W2e  = (const float*)d_in[4];
    const float* b2e  = (const float*)d_in[5];
    const float* W1f  = (const float*)d_in[6];
    const float* b1f  = (const float*)d_in[7];
    const float* W2f  = (const float*)d_in[8];
    const float* b2f  = (const float*)d_in[9];
    const int* batch  = (const int*)d_in[10];
    const int* eidx   = (const int*)d_in[11];
    float* out = (float*)d_out;

    const size_t N4 = (size_t)(NODES + EDGES) * EMB / 4;
    cvt_x_kernel<<<(int)((N4 + 255) / 256), 256>>>(x);

    prep_w1<<<dim3(16, 192), dim3(32, 8)>>>(W1e, W1f, out, out_size);

    const int ng_smem = 4 * NG_ST;  // 192 KB
    cudaFuncSetAttribute(node_gemm, cudaFuncAttributeMaxDynamicSharedMemorySize, ng_smem);
    node_gemm<<<dim3((NODES + 127) / 128, 16), 256, ng_smem>>>();

    const int fe_smem = FB_OFF + 3 * FB_ST;  // 128 KB A + 96 KB B = 224 KB
    cudaFuncSetAttribute(fused_edge, cudaFuncAttributeMaxDynamicSharedMemorySize, fe_smem);
    fused_edge<<<EDGES / 128, 256, fe_smem>>>(
        pos, b1e, W2e, b2e, b1f, W2f, b2f, batch, eidx, out);
}